// round 4
// baseline (speedup 1.0000x reference)
#include <cuda_runtime.h>
#include <cuda_bf16.h>
#include <float.h>

// Problem: out[b][c] = max over (h,w) of in[b][h][w][c]
//   in : [32, 224, 224, 128] f32, NHWC (C contiguous)
//   out: [32, 128] f32
// Pure HBM-streaming reduction: 822 MB read, 16 KB written.
//
// Layout: single wave of 608 persistent blocks (152 SMs x occ 4). Each block
// owns one contiguous chunk of the flattened B*HW row space. A chunk crosses
// a batch boundary at most once -> at most 2 accumulate/flush segments.

static constexpr int B  = 32;
static constexpr int HW = 224 * 224;       // 50176 rows per batch
static constexpr int C  = 128;
static constexpr int C4 = C / 4;           // 32 float4 groups per row
static constexpr long long R = (long long)B * HW;  // 1,605,632 global rows

static constexpr int THREADS = 256;        // 32 c4-lanes x 8 row-lanes
static constexpr int RLANES  = THREADS / C4;       // 8
static constexpr int GRID    = 152 * 4;    // 608 blocks = one full wave @ occ 4
static constexpr int CHUNK   = (int)((R + GRID - 1) / GRID);  // 2642 rows (< HW)
static constexpr int UNROLL  = 8;

__device__ __forceinline__ float4 f4max(float4 a, float4 b) {
    return make_float4(fmaxf(a.x, b.x), fmaxf(a.y, b.y),
                       fmaxf(a.z, b.z), fmaxf(a.w, b.w));
}

// Float atomic-max via monotone int/uint reinterpretation (init = -FLT_MAX).
__device__ __forceinline__ void atomicMaxF(float* addr, float v) {
    if (v >= 0.0f) {
        atomicMax(reinterpret_cast<int*>(addr), __float_as_int(v));
    } else {
        atomicMin(reinterpret_cast<unsigned int*>(addr), __float_as_uint(v));
    }
}

__global__ void init_out_kernel(float* __restrict__ out, int n) {
    int i = blockIdx.x * blockDim.x + threadIdx.x;
    if (i < n) out[i] = -FLT_MAX;
}

// Reduce global rows [lo, hi) for this thread's channel group.
// Thread's rows: lo + r, lo + r + 8, ... (8 row-lanes cover all rows)
__device__ __forceinline__ float4 reduce_rows(
    const float4* __restrict__ in4, int c4, long long lo, long long hi, int r)
{
    float4 m[UNROLL];
    #pragma unroll
    for (int i = 0; i < UNROLL; i++)
        m[i] = make_float4(-FLT_MAX, -FLT_MAX, -FLT_MAX, -FLT_MAX);

    long long row = lo + r;
    // 8 independent streaming LDG.128 per iteration (64 rows consumed)
    for (; row + (UNROLL - 1) * RLANES < hi; row += UNROLL * RLANES) {
        float4 v[UNROLL];
        #pragma unroll
        for (int i = 0; i < UNROLL; i++)
            v[i] = __ldcs(in4 + (row + i * RLANES) * C4 + c4);
        #pragma unroll
        for (int i = 0; i < UNROLL; i++)
            m[i] = f4max(m[i], v[i]);
    }
    for (; row < hi; row += RLANES)
        m[0] = f4max(m[0], __ldcs(in4 + row * C4 + c4));

    #pragma unroll
    for (int s = UNROLL / 2; s > 0; s >>= 1)
        #pragma unroll
        for (int i = 0; i < s; i++)
            m[i] = f4max(m[i], m[i + s]);
    return m[0];
}

// Block-wide combine of per-thread partials for one batch b, then atomics.
__device__ __forceinline__ void flush_block(
    float4* sm, float4 m, int b, float* __restrict__ out)
{
    sm[threadIdx.x] = m;
    __syncthreads();
    if (threadIdx.x < 128) sm[threadIdx.x] = f4max(sm[threadIdx.x], sm[threadIdx.x + 128]);
    __syncthreads();
    if (threadIdx.x < 64)  sm[threadIdx.x] = f4max(sm[threadIdx.x], sm[threadIdx.x + 64]);
    __syncthreads();
    if (threadIdx.x < 32) {
        float4 v = f4max(sm[threadIdx.x], sm[threadIdx.x + 32]);
        float* o = out + b * C + threadIdx.x * 4;
        atomicMaxF(o + 0, v.x);
        atomicMaxF(o + 1, v.y);
        atomicMaxF(o + 2, v.z);
        atomicMaxF(o + 3, v.w);
    }
    __syncthreads();   // sm reusable for a second flush
}

__global__ __launch_bounds__(THREADS, 4)   // 64 regs -> 8 LDG.128 in flight
void max_spatial_kernel(const float* __restrict__ in, float* __restrict__ out) {
    const int c4 = threadIdx.x & (C4 - 1);
    const int r  = threadIdx.x >> 5;

    const float4* in4 = reinterpret_cast<const float4*>(in);

    long long start = (long long)blockIdx.x * CHUNK;
    long long end   = start + CHUNK;
    if (end > R) end = R;
    if (start >= end) return;

    __shared__ float4 sm[THREADS];

    const int  b0    = (int)(start / HW);
    long long  bound = (long long)(b0 + 1) * HW;
    if (bound > end) bound = end;

    // Segment 1: batch b0
    float4 m = reduce_rows(in4, c4, start, bound, r);
    flush_block(sm, m, b0, out);

    // Segment 2: batch b0+1 (chunk crosses at most one boundary)
    if (bound < end) {
        float4 m2 = reduce_rows(in4, c4, bound, end, r);
        flush_block(sm, m2, b0 + 1, out);
    }
}

extern "C" void kernel_launch(void* const* d_in, const int* in_sizes, int n_in,
                              void* d_out, int out_size) {
    const float* in = (const float*)d_in[0];
    float* out = (float*)d_out;

    init_out_kernel<<<(out_size + 255) / 256, 256>>>(out, out_size);
    max_spatial_kernel<<<GRID, THREADS>>>(in, out);
}

// round 5
// speedup vs baseline: 1.0105x; 1.0105x over previous
#include <cuda_runtime.h>
#include <cuda_bf16.h>
#include <float.h>

// Problem: out[b][c] = max over (h,w) of in[b][h][w][c]
//   in : [32, 224, 224, 128] f32, NHWC (C contiguous)
//   out: [32, 128] f32
// Pure HBM-streaming reduction: 822 MB read, 16 KB written.
//
// Layout (R3-style, retuned for GB300's 152 SMs): grid (38, 32) = 1216 blocks
// = exactly 2 waves at occupancy 4. Strided row assignment within each batch
// gives fine-grained balancing; 2nd wave backfills slow SMs.

static constexpr int B  = 32;
static constexpr int HW = 224 * 224;   // 50176 spatial rows per batch
static constexpr int C  = 128;         // channels (contiguous)
static constexpr int C4 = C / 4;       // 32 float4 groups per row

static constexpr int THREADS = 256;    // 32 c4-lanes x 8 row-lanes
static constexpr int ROWS_PER_BLK = THREADS / C4;       // 8
static constexpr int GRID_X = 38;      // 38*32 = 1216 = 2 x (152 SMs x occ 4)
static constexpr int STRIDE = GRID_X * ROWS_PER_BLK;    // 304 rows
static constexpr int UNROLL = 8;

__device__ __forceinline__ float4 f4max(float4 a, float4 b) {
    return make_float4(fmaxf(a.x, b.x), fmaxf(a.y, b.y),
                       fmaxf(a.z, b.z), fmaxf(a.w, b.w));
}

// Float atomic-max via monotone int/uint reinterpretation (init = -FLT_MAX).
__device__ __forceinline__ void atomicMaxF(float* addr, float v) {
    if (v >= 0.0f) {
        atomicMax(reinterpret_cast<int*>(addr), __float_as_int(v));
    } else {
        atomicMin(reinterpret_cast<unsigned int*>(addr), __float_as_uint(v));
    }
}

__global__ void init_out_kernel(float* __restrict__ out, int n) {
    int i = blockIdx.x * blockDim.x + threadIdx.x;
    if (i < n) out[i] = -FLT_MAX;
}

__global__ __launch_bounds__(THREADS, 4)   // ~64 regs -> 8 LDG.128 in flight
void max_spatial_kernel(const float* __restrict__ in, float* __restrict__ out) {
    const int b   = blockIdx.y;
    const int c4  = threadIdx.x & (C4 - 1);   // float4 channel group 0..31
    const int r   = threadIdx.x >> 5;         // row lane 0..7

    // Base pointer for this batch + channel group (float4 units)
    const float4* base =
        reinterpret_cast<const float4*>(in + (size_t)b * HW * C) + c4;

    int row = blockIdx.x * ROWS_PER_BLK + r;

    float4 m[UNROLL];
    #pragma unroll
    for (int i = 0; i < UNROLL; i++)
        m[i] = make_float4(-FLT_MAX, -FLT_MAX, -FLT_MAX, -FLT_MAX);

    // 8 independent streaming LDG.128 in flight per thread (MLP 8).
    for (; row + (UNROLL - 1) * STRIDE < HW; row += UNROLL * STRIDE) {
        float4 v[UNROLL];
        #pragma unroll
        for (int i = 0; i < UNROLL; i++)
            v[i] = __ldcs(base + (size_t)(row + i * STRIDE) * C4);
        #pragma unroll
        for (int i = 0; i < UNROLL; i++)
            m[i] = f4max(m[i], v[i]);
    }
    for (; row < HW; row += STRIDE) {
        m[0] = f4max(m[0], __ldcs(base + (size_t)row * C4));
    }

    // Tree-combine the 8 accumulators
    #pragma unroll
    for (int s = UNROLL / 2; s > 0; s >>= 1)
        #pragma unroll
        for (int i = 0; i < s; i++)
            m[i] = f4max(m[i], m[i + s]);

    // Reduce across the 8 row-lanes sharing this c4 (tid, tid+32, ... tid+224)
    __shared__ float4 sm[THREADS];
    sm[threadIdx.x] = m[0];
    __syncthreads();
    if (threadIdx.x < 128) sm[threadIdx.x] = f4max(sm[threadIdx.x], sm[threadIdx.x + 128]);
    __syncthreads();
    if (threadIdx.x < 64)  sm[threadIdx.x] = f4max(sm[threadIdx.x], sm[threadIdx.x + 64]);
    __syncthreads();
    if (threadIdx.x < 32) {
        float4 v = f4max(sm[threadIdx.x], sm[threadIdx.x + 32]);
        float* o = out + b * C + threadIdx.x * 4;
        atomicMaxF(o + 0, v.x);
        atomicMaxF(o + 1, v.y);
        atomicMaxF(o + 2, v.z);
        atomicMaxF(o + 3, v.w);
    }
}

extern "C" void kernel_launch(void* const* d_in, const int* in_sizes, int n_in,
                              void* d_out, int out_size) {
    const float* in = (const float*)d_in[0];
    float* out = (float*)d_out;

    init_out_kernel<<<(out_size + 255) / 256, 256>>>(out, out_size);

    dim3 grid(GRID_X, B);
    max_spatial_kernel<<<grid, THREADS>>>(in, out);
}

// round 6
// speedup vs baseline: 1.0190x; 1.0084x over previous
#include <cuda_runtime.h>
#include <cuda_bf16.h>
#include <float.h>

// Problem: out[b][c] = max over (h,w) of in[b][h][w][c]
//   in : [32, 224, 224, 128] f32, NHWC (C contiguous)
//   out: [32, 128] f32
// Pure HBM-streaming reduction: 822 MB read, 16 KB written.
//
// Single kernel launch: grid (38, 32) = 1216 blocks = 2 waves @ occ 4 on
// 152 SMs. Per-block partials go to a __device__ scratch array; the last
// block to finish each batch (arrival counter) combines the 38 partials and
// writes the output. Counters self-reset -> graph-replay deterministic.

static constexpr int B  = 32;
static constexpr int HW = 224 * 224;   // 50176 spatial rows per batch
static constexpr int C  = 128;         // channels (contiguous)
static constexpr int C4 = C / 4;       // 32 float4 groups per row

static constexpr int THREADS = 256;    // 32 c4-lanes x 8 row-lanes
static constexpr int ROWS_PER_BLK = THREADS / C4;       // 8
static constexpr int GRID_X = 38;      // 38*32 = 1216 = 2 x (152 SMs x occ 4)
static constexpr int STRIDE = GRID_X * ROWS_PER_BLK;    // 304 rows
static constexpr int UNROLL = 8;

// Static device scratch (no dynamic allocation allowed).
__device__ float4 g_partials[B][GRID_X][C4];   // 622 KB
__device__ int    g_arrival[B];                // zero-initialized at load

__device__ __forceinline__ float4 f4max(float4 a, float4 b) {
    return make_float4(fmaxf(a.x, b.x), fmaxf(a.y, b.y),
                       fmaxf(a.z, b.z), fmaxf(a.w, b.w));
}

__global__ __launch_bounds__(THREADS, 4)   // ~64 regs -> 8 LDG.128 in flight
void max_spatial_kernel(const float* __restrict__ in, float* __restrict__ out) {
    const int b   = blockIdx.y;
    const int bx  = blockIdx.x;
    const int c4  = threadIdx.x & (C4 - 1);   // float4 channel group 0..31
    const int r   = threadIdx.x >> 5;         // row lane 0..7

    // Base pointer for this batch + channel group (float4 units)
    const float4* base =
        reinterpret_cast<const float4*>(in + (size_t)b * HW * C) + c4;

    int row = bx * ROWS_PER_BLK + r;

    float4 m[UNROLL];
    #pragma unroll
    for (int i = 0; i < UNROLL; i++)
        m[i] = make_float4(-FLT_MAX, -FLT_MAX, -FLT_MAX, -FLT_MAX);

    // 8 independent streaming LDG.128 in flight per thread (MLP 8).
    for (; row + (UNROLL - 1) * STRIDE < HW; row += UNROLL * STRIDE) {
        float4 v[UNROLL];
        #pragma unroll
        for (int i = 0; i < UNROLL; i++)
            v[i] = __ldcs(base + (size_t)(row + i * STRIDE) * C4);
        #pragma unroll
        for (int i = 0; i < UNROLL; i++)
            m[i] = f4max(m[i], v[i]);
    }
    for (; row < HW; row += STRIDE) {
        m[0] = f4max(m[0], __ldcs(base + (size_t)row * C4));
    }

    // Tree-combine the 8 accumulators
    #pragma unroll
    for (int s = UNROLL / 2; s > 0; s >>= 1)
        #pragma unroll
        for (int i = 0; i < s; i++)
            m[i] = f4max(m[i], m[i + s]);

    // Reduce across the 8 row-lanes sharing this c4 (tid, tid+32, ... tid+224)
    __shared__ float4 sm[THREADS];
    sm[threadIdx.x] = m[0];
    __syncthreads();
    if (threadIdx.x < 128) sm[threadIdx.x] = f4max(sm[threadIdx.x], sm[threadIdx.x + 128]);
    __syncthreads();
    if (threadIdx.x < 64)  sm[threadIdx.x] = f4max(sm[threadIdx.x], sm[threadIdx.x + 64]);
    __syncthreads();
    if (threadIdx.x < 32) {
        float4 v = f4max(sm[threadIdx.x], sm[threadIdx.x + 32]);
        g_partials[b][bx][threadIdx.x] = v;     // non-atomic STG.128
    }

    // Make partial visible, then count arrivals for this batch.
    __threadfence();
    __shared__ int is_last;
    if (threadIdx.x == 0) {
        int old = atomicAdd(&g_arrival[b], 1);
        is_last = (old == GRID_X - 1);
    }
    __syncthreads();

    // Last block of this batch: combine the 38 partials, write out, reset.
    if (is_last) {
        if (threadIdx.x < C4) {
            float4 acc = g_partials[b][0][threadIdx.x];
            #pragma unroll
            for (int i = 1; i < GRID_X; i++)
                acc = f4max(acc, g_partials[b][i][threadIdx.x]);
            reinterpret_cast<float4*>(out)[b * C4 + threadIdx.x] = acc;
        }
        if (threadIdx.x == 0)
            g_arrival[b] = 0;   // self-reset for next graph replay
    }
}

extern "C" void kernel_launch(void* const* d_in, const int* in_sizes, int n_in,
                              void* d_out, int out_size) {
    const float* in = (const float*)d_in[0];
    float* out = (float*)d_out;

    dim3 grid(GRID_X, B);
    max_spatial_kernel<<<grid, THREADS>>>(in, out);
}